// round 1
// baseline (speedup 1.0000x reference)
#include <cuda_runtime.h>

// DenseCRFLoss on GB300.
// loss = -(1/N) * sum_{n,k,p,q} S[n,k,p] * exp(-0.5*||f_p - f_q||^2) * S[n,k,q]
// out  = WEIGHT * loss, WEIGHT = 2e-9, N = 4.
//
// Exponent rewritten in log2 units:
//   K_pq = exp2( f'_p . f'_q + h'_p + h'_q ),  f' = f*sqrt(log2e), h' = -0.5*log2e*|f|^2

#define N_IMG   4
#define H_IN    128
#define W_IN    128
#define HS      64
#define P       4096          // HS*HS
#define TP      4             // p's per thread (register-resident)
#define THREADS 256
#define PB      1024          // p's per block = THREADS*TP
#define NPB     4             // P / PB
#define QR      128           // q's per block
#define NQ      32            // P / QR
#define NBLOCKS (N_IMG*NPB*NQ)   // 512

__device__ float g_feat[N_IMG * P * 8];     // AoS: [f0,f1,f2,f3,f4,h,s0,s1] per pixel
__device__ float g_partial[NBLOCKS];

__device__ __forceinline__ float ex2(float x) {
    float r;
    asm("ex2.approx.f32 %0, %1;" : "=f"(r) : "f"(x));
    return r;
}

// ---------------------------------------------------------------------------
// Preprocess: nearest-downsample image, bilinear-downsample seg (== 2x2 mean
// at scale 0.5 / align_corners=False), build scaled feature records.
// ---------------------------------------------------------------------------
__global__ void crf_prep(const float* __restrict__ img, const float* __restrict__ seg) {
    int idx = blockIdx.x * blockDim.x + threadIdx.x;   // over N_IMG * P
    if (idx >= N_IMG * P) return;
    int n = idx >> 12;
    int p = idx & (P - 1);
    int y = p >> 6, x = p & 63;

    const float LOG2E = 1.44269504088896340736f;
    const float SQ    = 1.20112240878644981f;   // sqrt(LOG2E)

    int yi = 2 * y, xi = 2 * x;
    const float* ib = img + (size_t)n * 3 * (H_IN * W_IN);
    float r = ib[0 * 16384 + yi * W_IN + xi];
    float g = ib[1 * 16384 + yi * W_IN + xi];
    float b = ib[2 * 16384 + yi * W_IN + xi];

    float f0 = (float)x * (1.0f / 50.0f);   // SIGMA_XY * SCALE = 50
    float f1 = (float)y * (1.0f / 50.0f);
    float f2 = r * (1.0f / 15.0f);          // SIGMA_RGB = 15
    float f3 = g * (1.0f / 15.0f);
    float f4 = b * (1.0f / 15.0f);
    float nrm = f0*f0 + f1*f1 + f2*f2 + f3*f3 + f4*f4;
    float h = -0.5f * LOG2E * nrm;

    const float* sb = seg + (size_t)n * 2 * 16384;
    float s0 = 0.25f * (sb[yi*W_IN + xi]       + sb[yi*W_IN + xi + 1] +
                        sb[(yi+1)*W_IN + xi]   + sb[(yi+1)*W_IN + xi + 1]);
    float s1 = 0.25f * (sb[16384 + yi*W_IN + xi]     + sb[16384 + yi*W_IN + xi + 1] +
                        sb[16384 + (yi+1)*W_IN + xi] + sb[16384 + (yi+1)*W_IN + xi + 1]);

    float* o = g_feat + (size_t)idx * 8;
    o[0] = f0 * SQ; o[1] = f1 * SQ; o[2] = f2 * SQ; o[3] = f3 * SQ; o[4] = f4 * SQ;
    o[5] = h;       o[6] = s0;      o[7] = s1;
}

// ---------------------------------------------------------------------------
// Main pair kernel: each block handles (n, 1024 p's, 128 q's).
// TP=4 p-records in registers; q chunk in smem as float4 pairs.
// ---------------------------------------------------------------------------
__global__ void __launch_bounds__(THREADS) crf_main() {
    int bx = blockIdx.x;
    int qi = bx % NQ;
    int pb = (bx / NQ) % NPB;
    int n  = bx / (NQ * NPB);

    const float4* feat4 = (const float4*)g_feat;   // 2 float4 per pixel record
    int pBase = pb * PB;
    int qBase = qi * QR;

    float4 pa[TP], pc[TP];
    #pragma unroll
    for (int i = 0; i < TP; i++) {
        int p = pBase + threadIdx.x + i * THREADS;
        pa[i] = feat4[(size_t)(n * P + p) * 2];
        pc[i] = feat4[(size_t)(n * P + p) * 2 + 1];
    }

    __shared__ float4 sq[QR * 2];
    for (int j = threadIdx.x; j < QR * 2; j += THREADS)
        sq[j] = feat4[(size_t)(n * P + qBase) * 2 + j];
    __syncthreads();

    float acc = 0.0f;
    #pragma unroll 2
    for (int q = 0; q < QR; q++) {
        float4 a = sq[2 * q];
        float4 b = sq[2 * q + 1];
        #pragma unroll
        for (int i = 0; i < TP; i++) {
            float L = pc[i].y + b.y;                 // h'_p + h'_q
            L = fmaf(pa[i].x, a.x, L);
            L = fmaf(pa[i].y, a.y, L);
            L = fmaf(pa[i].z, a.z, L);
            L = fmaf(pa[i].w, a.w, L);
            L = fmaf(pc[i].x, b.x, L);
            float k = ex2(L);
            float w = pc[i].z * b.z;
            w = fmaf(pc[i].w, b.w, w);
            acc = fmaf(k, w, acc);
        }
    }

    // block reduce (deterministic, no atomics)
    __shared__ float red[THREADS / 32];
    #pragma unroll
    for (int o = 16; o; o >>= 1)
        acc += __shfl_down_sync(0xffffffffu, acc, o);
    if ((threadIdx.x & 31) == 0) red[threadIdx.x >> 5] = acc;
    __syncthreads();
    if (threadIdx.x < THREADS / 32) {
        float v = red[threadIdx.x];
        #pragma unroll
        for (int o = (THREADS / 64); o; o >>= 1)
            v += __shfl_down_sync(0x000000ffu, v, o);
        if (threadIdx.x == 0) g_partial[bx] = v;
    }
}

// ---------------------------------------------------------------------------
// Final reduction: sum 512 partials, scale, write the scalar.
// ---------------------------------------------------------------------------
__global__ void crf_finalize(float* __restrict__ out) {
    __shared__ float red[NBLOCKS / 32];   // 16
    float v = g_partial[threadIdx.x];     // 512 threads
    #pragma unroll
    for (int o = 16; o; o >>= 1)
        v += __shfl_down_sync(0xffffffffu, v, o);
    if ((threadIdx.x & 31) == 0) red[threadIdx.x >> 5] = v;
    __syncthreads();
    if (threadIdx.x < 16) {
        float t = red[threadIdx.x];
        #pragma unroll
        for (int o = 8; o; o >>= 1)
            t += __shfl_down_sync(0x0000ffffu, t, o);
        if (threadIdx.x == 0)
            out[0] = -(2e-9f / (float)N_IMG) * t;   // WEIGHT * (-sum / N)
    }
}

extern "C" void kernel_launch(void* const* d_in, const int* in_sizes, int n_in,
                              void* d_out, int out_size) {
    const float* images = (const float*)d_in[0];
    const float* segs   = (const float*)d_in[1];
    float* out = (float*)d_out;

    crf_prep<<<(N_IMG * P + THREADS - 1) / THREADS, THREADS>>>(images, segs);
    crf_main<<<NBLOCKS, THREADS>>>();
    crf_finalize<<<1, NBLOCKS>>>(out);
}

// round 4
// speedup vs baseline: 1.8633x; 1.8633x over previous
#include <cuda_runtime.h>

// DenseCRFLoss on GB300 — R3: symmetric tiling + f32x2 packed FMA + fused prep.
// (R2 fixed: f32x2 carried in unsigned long long for asm "l" constraint.)
//
// loss = -(1/N) * sum_{n,k,p,q} S[n,k,p] * exp(-0.5*||f_p - f_q||^2) * S[n,k,q]
// out  = WEIGHT * loss, WEIGHT = 2e-9, N = 4.
// Exponent in log2 units: K_pq = exp2( f'_p . f'_q + h'_p + h'_q ),
//   f' = f*sqrt(log2e), h' = -0.5*log2e*|f|^2.
// Symmetry: total = sum(diag tiles) + 2*sum(strict-upper tiles).

#define N_IMG   4
#define HS      64
#define P       4096
#define TS      512             // square tile size
#define NT      8               // P / TS
#define NTRI    36              // NT*(NT+1)/2 upper-tri tiles
#define NBLOCKS (N_IMG * NTRI)  // 144  (one wave on 148 SMs)
#define THREADS 256
#define TP      2               // p's per thread

typedef unsigned long long u64;

__device__ float g_partial[NBLOCKS];

__device__ __forceinline__ float ex2f(float x) {
    float r; asm("ex2.approx.f32 %0, %1;" : "=f"(r) : "f"(x)); return r;
}
__device__ __forceinline__ u64 fma2(u64 a, u64 b, u64 c) {
    u64 d; asm("fma.rn.f32x2 %0, %1, %2, %3;" : "=l"(d) : "l"(a), "l"(b), "l"(c)); return d;
}
__device__ __forceinline__ u64 add2(u64 a, u64 b) {
    u64 d; asm("add.rn.f32x2 %0, %1, %2;" : "=l"(d) : "l"(a), "l"(b)); return d;
}
__device__ __forceinline__ u64 mul2(u64 a, u64 b) {
    u64 d; asm("mul.rn.f32x2 %0, %1, %2;" : "=l"(d) : "l"(a), "l"(b)); return d;
}
__device__ __forceinline__ u64 pack2(float lo, float hi) {
    u64 d; asm("mov.b64 %0, {%1, %2};" : "=l"(d) : "f"(lo), "f"(hi)); return d;
}
__device__ __forceinline__ float2 unpack2(u64 v) {
    float2 r; asm("mov.b64 {%0, %1}, %2;" : "=f"(r.x), "=f"(r.y) : "l"(v)); return r;
}

// Feature record for pixel `pix` (row-major in the 64x64 downscaled grid) of image n.
// f[0..4] = scaled feature * sqrt(log2e), f[5] = h' = -0.5*log2e*|f|^2, f[6..7] = seg.
__device__ __forceinline__ void feat(const float* __restrict__ img,
                                     const float* __restrict__ seg,
                                     int n, int pix, float f[8]) {
    const float LOG2E = 1.44269504088896340736f;
    const float SQ    = 1.20112240878644981f;   // sqrt(LOG2E)
    int y = pix >> 6, x = pix & 63;
    int yi = 2 * y, xi = 2 * x;
    int o = yi * 128 + xi;

    const float* ib = img + (size_t)n * 3 * 16384;
    float r = ib[o];
    float g = ib[16384 + o];
    float b = ib[32768 + o];

    float f0 = (float)x * (1.0f / 50.0f);   // SIGMA_XY * SCALE = 50
    float f1 = (float)y * (1.0f / 50.0f);
    float f2 = r * (1.0f / 15.0f);          // SIGMA_RGB = 15
    float f3 = g * (1.0f / 15.0f);
    float f4 = b * (1.0f / 15.0f);
    float h = -0.5f * LOG2E * (f0*f0 + f1*f1 + f2*f2 + f3*f3 + f4*f4);

    const float* sb = seg + (size_t)n * 2 * 16384;
    float s0 = 0.25f * (sb[o] + sb[o+1] + sb[o+128] + sb[o+129]);
    float s1 = 0.25f * (sb[16384+o] + sb[16384+o+1] + sb[16384+o+128] + sb[16384+o+129]);

    f[0] = f0 * SQ; f[1] = f1 * SQ; f[2] = f2 * SQ; f[3] = f3 * SQ; f[4] = f4 * SQ;
    f[5] = h;       f[6] = s0;      f[7] = s1;
}

// ---------------------------------------------------------------------------
// Main: block = (image n, upper-tri tile (i,j)). p-tile i in registers (TP=2
// per thread, components broadcast as f32x2 {c,c}); q-tile j in smem packed as
// f32x2 over consecutive q-pairs.
// ---------------------------------------------------------------------------
__global__ void __launch_bounds__(THREADS)
crf_main(const float* __restrict__ img, const float* __restrict__ seg) {
    __shared__ u64 sq[(TS / 2) * 8];   // 256 q-pairs x 8 packed components = 16KB

    int blk = blockIdx.x;
    int n = blk / NTRI;
    int t = blk % NTRI;
    int i = 0;
    {   // upper-triangle (i,j), i <= j
        int rem = t;
        while (rem >= NT - i) { rem -= NT - i; i++; }
        t = i + rem;        // t now = j
    }
    int j = t;
    int tid = threadIdx.x;

    // Fill q-tile smem in packed-pair layout.
    for (int k = tid; k < TS; k += THREADS) {
        float f[8];
        feat(img, seg, n, j * TS + k, f);
        int pr = k >> 1, half = k & 1;
        float* s = reinterpret_cast<float*>(&sq[pr * 8]);
        #pragma unroll
        for (int c = 0; c < 8; c++) s[c * 2 + half] = f[c];
    }

    // p features in registers, broadcast-packed {c,c}.
    u64 px[TP][5], hp[TP], s0p[TP], s1p[TP], acc[TP];
    #pragma unroll
    for (int tp = 0; tp < TP; tp++) {
        float f[8];
        feat(img, seg, n, i * TS + tid + tp * THREADS, f);
        #pragma unroll
        for (int c = 0; c < 5; c++) px[tp][c] = pack2(f[c], f[c]);
        hp[tp]  = pack2(f[5], f[5]);
        s0p[tp] = pack2(f[6], f[6]);
        s1p[tp] = pack2(f[7], f[7]);
        acc[tp] = pack2(0.0f, 0.0f);
    }
    __syncthreads();

    #pragma unroll 2
    for (int jq = 0; jq < TS / 2; jq++) {
        const ulonglong2* qd = reinterpret_cast<const ulonglong2*>(&sq[jq * 8]);
        ulonglong2 A = qd[0];   // {f0 pair, f1 pair}
        ulonglong2 B = qd[1];   // {f2 pair, f3 pair}
        ulonglong2 C = qd[2];   // {f4 pair, h  pair}
        ulonglong2 D = qd[3];   // {s0 pair, s1 pair}
        #pragma unroll
        for (int tp = 0; tp < TP; tp++) {
            u64 L = add2(hp[tp], C.y);
            L = fma2(px[tp][0], A.x, L);
            L = fma2(px[tp][1], A.y, L);
            L = fma2(px[tp][2], B.x, L);
            L = fma2(px[tp][3], B.y, L);
            L = fma2(px[tp][4], C.x, L);
            float2 Lf = unpack2(L);
            u64 k2 = pack2(ex2f(Lf.x), ex2f(Lf.y));
            u64 w = mul2(s0p[tp], D.x);
            w = fma2(s1p[tp], D.y, w);
            acc[tp] = fma2(k2, w, acc[tp]);
        }
    }

    float a = 0.0f;
    #pragma unroll
    for (int tp = 0; tp < TP; tp++) {
        float2 av = unpack2(acc[tp]);
        a += av.x + av.y;
    }
    if (i != j) a *= 2.0f;   // symmetry weight for strict-upper tiles

    // Deterministic block reduction.
    __shared__ float red[THREADS / 32];
    #pragma unroll
    for (int o = 16; o; o >>= 1) a += __shfl_down_sync(0xffffffffu, a, o);
    if ((tid & 31) == 0) red[tid >> 5] = a;
    __syncthreads();
    if (tid < THREADS / 32) {
        float v = red[tid];
        #pragma unroll
        for (int o = THREADS / 64; o; o >>= 1) v += __shfl_down_sync(0x000000ffu, v, o);
        if (tid == 0) g_partial[blk] = v;
    }
}

// ---------------------------------------------------------------------------
// Final reduction over 144 partials.
// ---------------------------------------------------------------------------
__global__ void crf_finalize(float* __restrict__ out) {
    __shared__ float red[8];
    float v = (threadIdx.x < NBLOCKS) ? g_partial[threadIdx.x] : 0.0f;
    #pragma unroll
    for (int o = 16; o; o >>= 1) v += __shfl_down_sync(0xffffffffu, v, o);
    if ((threadIdx.x & 31) == 0) red[threadIdx.x >> 5] = v;
    __syncthreads();
    if (threadIdx.x < 8) {
        float t = red[threadIdx.x];
        #pragma unroll
        for (int o = 4; o; o >>= 1) t += __shfl_down_sync(0x000000ffu, t, o);
        if (threadIdx.x == 0)
            out[0] = -(2e-9f / (float)N_IMG) * t;   // WEIGHT * (-sum / N)
    }
}

extern "C" void kernel_launch(void* const* d_in, const int* in_sizes, int n_in,
                              void* d_out, int out_size) {
    const float* images = (const float*)d_in[0];
    const float* segs   = (const float*)d_in[1];
    float* out = (float*)d_out;

    crf_main<<<NBLOCKS, THREADS>>>(images, segs);
    crf_finalize<<<1, 256>>>(out);
}